// round 5
// baseline (speedup 1.0000x reference)
#include <cuda_runtime.h>

// Problem constants (fixed by the reference: B=4, C=8, H=W=1024, R=1 cross kernel, wrap pad)
constexpr int Hh = 1024;
constexpr int Ww = 1024;
constexpr int PLANE = Hh * Ww;          // 1,048,576

// Accurate fp32 exp (Cody-Waite reduction + cephes degree-6 poly, ~1 ulp).
__device__ __forceinline__ float exp_acc(float x) {
    x = fminf(fmaxf(x, -87.3f), 88.0f);
    float n = rintf(x * 1.44269504088896341f);
    float r = fmaf(n, -0.693359375f, x);        // Cody-Waite hi
    r = fmaf(n, 2.12194440e-4f, r);             // Cody-Waite lo
    float rr = r * r;
    float y = 1.9875691500e-4f;
    y = fmaf(y, r, 1.3981999507e-3f);
    y = fmaf(y, r, 8.3334519073e-3f);
    y = fmaf(y, r, 4.1665795894e-2f);
    y = fmaf(y, r, 1.6666665459e-1f);
    y = fmaf(y, r, 5.0000001201e-1f);
    y = fmaf(y, rr, r);
    y = y + 1.0f;
    float sc = __int_as_float(((int)n + 127) << 23);
    return y * sc;
}

__device__ __forceinline__ float flip_one(float s, float J, float bf, float r, bool drop) {
    float de = 2.0f * s * J;
    bool flip;
    if (de <= 0.0f) {
        flip = drop;                            // p = 1, rand in [0,1) < 1 always
    } else {
        float p = exp_acc(-de * bf);
        flip = (r < p) && drop;
    }
    return flip ? -s : s;
}

__device__ __forceinline__ float4 ld_cs4(const float* p) {
    return __ldcs(reinterpret_cast<const float4*>(p));
}

// One block = one (batch, row): 256 threads x 4 pixels = 1024 = full row.
// Center rows for all 8 channels are staged in smem; horizontal neighbors
// (incl. the row wrap) and pass-2 center reads all come from smem.
__global__ __launch_bounds__(256, 6) void ising_step_kernel(
    const float* __restrict__ x,      // (4, 9, 1024, 1024): s = ch 0..7, b = ch 8
    const float* __restrict__ rnd,    // (4, 8, 1024, 1024)
    const float* __restrict__ drop,   // (1024, 1024)
    float* __restrict__ out)          // (4, 9, 1024, 1024)
{
    __shared__ float srow[8][Ww];     // 32 KB: center row per channel

    int h = blockIdx.x & (Hh - 1);
    int b = blockIdx.x >> 10;
    int w = threadIdx.x * 4;

    int rowc = h * Ww + w;                                  // this thread's 4 pixels
    int du = (((h + Hh - 1) & (Hh - 1)) - h) * Ww;          // relative offset: up row (wrap)
    int dd = (((h + 1) & (Hh - 1)) - h) * Ww;               // relative offset: down row (wrap)
    int wl = (w + Ww - 1) & (Ww - 1);                       // left-of-pixel-0 column (wrap)
    int wr = (w + 4) & (Ww - 1);                            // right-of-pixel-3 column (wrap)

    const float* xb = x + b * 9 * PLANE + rowc;

    // Pass 1a: stage centers into smem, accumulate the vertical part of J.
    // All global loads here are independent -> high MLP.
    float4 J = make_float4(0.f, 0.f, 0.f, 0.f);
    {
        const float* sp = xb;
        #pragma unroll
        for (int c = 0; c < 8; c++, sp += PLANE) {
            float4 cc = ld_cs4(sp);              // read exactly once from global
            float4 up = ld_cs4(sp + du);
            float4 dn = ld_cs4(sp + dd);
            *reinterpret_cast<float4*>(&srow[c][w]) = cc;
            J.x += up.x + dn.x;
            J.y += up.y + dn.y;
            J.z += up.z + dn.z;
            J.w += up.w + dn.w;
        }
    }

    // Field b and dropout mask for these 4 pixels (independent of the sync)
    float4 bf = ld_cs4(xb + 8 * PLANE);
    float4 dv = ld_cs4(drop + rowc);
    bool d0 = dv.x > 0.5f, d1 = dv.y > 0.5f, d2 = dv.z > 0.5f, d3 = dv.w > 0.5f;

    __syncthreads();

    // Pass 1b: horizontal part of J from smem (wrap is in-block: full row staged).
    #pragma unroll
    for (int c = 0; c < 8; c++) {
        float4 cc = *reinterpret_cast<const float4*>(&srow[c][w]);
        float lf = srow[c][wl];
        float rt = srow[c][wr];
        J.x += lf   + cc.y;
        J.y += cc.x + cc.z;
        J.z += cc.y + cc.w;
        J.w += cc.z + rt;
    }

    float* ob = out + b * 9 * PLANE + rowc;
    // Pass-through channel 8 (the field)
    *reinterpret_cast<float4*>(ob + 8 * PLANE) = bf;

    // Pass 2: flips. Centers come from smem (no global re-read), rand streams once.
    const float* rp = rnd + b * 8 * PLANE + rowc;
    {
        float* op = ob;
        #pragma unroll
        for (int c = 0; c < 8; c++, op += PLANE, rp += PLANE) {
            float4 cc = *reinterpret_cast<const float4*>(&srow[c][w]);
            float4 rv = ld_cs4(rp);
            float4 o;
            o.x = flip_one(cc.x, J.x, bf.x, rv.x, d0);
            o.y = flip_one(cc.y, J.y, bf.y, rv.y, d1);
            o.z = flip_one(cc.z, J.z, bf.z, rv.z, d2);
            o.w = flip_one(cc.w, J.w, bf.w, rv.w, d3);
            *reinterpret_cast<float4*>(op) = o;
        }
    }
}

extern "C" void kernel_launch(void* const* d_in, const int* in_sizes, int n_in,
                              void* d_out, int out_size) {
    const float* x    = (const float*)d_in[0];   // (4,9,1024,1024)
    const float* rnd  = (const float*)d_in[1];   // (4,8,1024,1024)
    const float* drop = (const float*)d_in[2];   // (1024,1024)
    // d_in[3] = nn_kernel: fixed cross structure, baked into the kernel
    float* out = (float*)d_out;

    int grid = 4 * Hh;                           // one block per (batch, row) = 4096
    ising_step_kernel<<<grid, 256>>>(x, rnd, drop, out);
}

// round 6
// speedup vs baseline: 1.3378x; 1.3378x over previous
#include <cuda_runtime.h>

// Problem constants (fixed by the reference: B=4, C=8, H=W=1024, R=1 cross kernel, wrap pad)
constexpr int Hh = 1024;
constexpr int Ww = 1024;
constexpr int PLANE = Hh * Ww;          // 1,048,576

// Accurate fp32 exp (Cody-Waite reduction + cephes degree-6 poly, ~1 ulp).
__device__ __forceinline__ float exp_acc(float x) {
    x = fminf(fmaxf(x, -87.3f), 88.0f);
    float n = rintf(x * 1.44269504088896341f);
    float r = fmaf(n, -0.693359375f, x);        // Cody-Waite hi
    r = fmaf(n, 2.12194440e-4f, r);             // Cody-Waite lo
    float rr = r * r;
    float y = 1.9875691500e-4f;
    y = fmaf(y, r, 1.3981999507e-3f);
    y = fmaf(y, r, 8.3334519073e-3f);
    y = fmaf(y, r, 4.1665795894e-2f);
    y = fmaf(y, r, 1.6666665459e-1f);
    y = fmaf(y, r, 5.0000001201e-1f);
    y = fmaf(y, rr, r);
    y = y + 1.0f;
    float sc = __int_as_float(((int)n + 127) << 23);
    return y * sc;
}

__device__ __forceinline__ float flip_one(float s, float J, float bf, float r, bool drop) {
    float de = 2.0f * s * J;
    bool flip;
    if (de <= 0.0f) {
        flip = drop;                            // p = 1, rand in [0,1) < 1 always
    } else {
        float p = exp_acc(-de * bf);
        flip = (r < p) && drop;
    }
    return flip ? -s : s;
}

__device__ __forceinline__ float4 ld4(const float* p) {
    return *reinterpret_cast<const float4*>(p);
}
__device__ __forceinline__ float4 ld_cs4(const float* p) {
    return __ldcs(reinterpret_cast<const float4*>(p));
}

// One block = one (batch, row): 256 threads x 4 pixels = 1024 = full row.
// Center rows for all 8 channels are staged in smem; horizontal neighbors
// (incl. the row wrap) and pass-2 center reads all come from smem.
// Cache policy: default for everything in x (s-lines are read 3x across
// adjacent-row blocks -> must fill L2 normally); .cs ONLY for rand.
__global__ __launch_bounds__(256, 6) void ising_step_kernel(
    const float* __restrict__ x,      // (4, 9, 1024, 1024): s = ch 0..7, b = ch 8
    const float* __restrict__ rnd,    // (4, 8, 1024, 1024)
    const float* __restrict__ drop,   // (1024, 1024)
    float* __restrict__ out)          // (4, 9, 1024, 1024)
{
    __shared__ float srow[8][Ww];     // 32 KB: center row per channel

    int h = blockIdx.x & (Hh - 1);
    int b = blockIdx.x >> 10;
    int w = threadIdx.x * 4;

    int rowc = h * Ww + w;                                  // this thread's 4 pixels
    int du = (((h + Hh - 1) & (Hh - 1)) - h) * Ww;          // relative offset: up row (wrap)
    int dd = (((h + 1) & (Hh - 1)) - h) * Ww;               // relative offset: down row (wrap)
    int wl = (w + Ww - 1) & (Ww - 1);                       // left-of-pixel-0 column (wrap)
    int wr = (w + 4) & (Ww - 1);                            // right-of-pixel-3 column (wrap)

    const float* xb = x + b * 9 * PLANE + rowc;

    // Pass 1a: stage centers into smem, accumulate the vertical part of J.
    // All global loads here are independent -> high MLP.
    float4 J = make_float4(0.f, 0.f, 0.f, 0.f);
    {
        const float* sp = xb;
        #pragma unroll
        for (int c = 0; c < 8; c++, sp += PLANE) {
            float4 cc = ld4(sp);                 // default: fills L2 for neighbor rows
            float4 up = ld4(sp + du);            // default: L2 hit on line filled by row h-1
            float4 dn = ld4(sp + dd);
            *reinterpret_cast<float4*>(&srow[c][w]) = cc;
            J.x += up.x + dn.x;
            J.y += up.y + dn.y;
            J.z += up.z + dn.z;
            J.w += up.w + dn.w;
        }
    }

    // Field b and dropout mask for these 4 pixels (independent of the sync)
    float4 bf = ld4(xb + 8 * PLANE);
    float4 dv = ld4(drop + rowc);
    bool d0 = dv.x > 0.5f, d1 = dv.y > 0.5f, d2 = dv.z > 0.5f, d3 = dv.w > 0.5f;

    __syncthreads();

    // Pass 1b: horizontal part of J from smem (wrap is in-block: full row staged).
    #pragma unroll
    for (int c = 0; c < 8; c++) {
        float4 cc = *reinterpret_cast<const float4*>(&srow[c][w]);
        float lf = srow[c][wl];
        float rt = srow[c][wr];
        J.x += lf   + cc.y;
        J.y += cc.x + cc.z;
        J.z += cc.y + cc.w;
        J.w += cc.z + rt;
    }

    float* ob = out + b * 9 * PLANE + rowc;
    // Pass-through channel 8 (the field)
    *reinterpret_cast<float4*>(ob + 8 * PLANE) = bf;

    // Pass 2: flips. Centers come from smem (no global re-read); rand streams once (.cs).
    const float* rp = rnd + b * 8 * PLANE + rowc;
    {
        float* op = ob;
        #pragma unroll
        for (int c = 0; c < 8; c++, op += PLANE, rp += PLANE) {
            float4 cc = *reinterpret_cast<const float4*>(&srow[c][w]);
            float4 rv = ld_cs4(rp);
            float4 o;
            o.x = flip_one(cc.x, J.x, bf.x, rv.x, d0);
            o.y = flip_one(cc.y, J.y, bf.y, rv.y, d1);
            o.z = flip_one(cc.z, J.z, bf.z, rv.z, d2);
            o.w = flip_one(cc.w, J.w, bf.w, rv.w, d3);
            *reinterpret_cast<float4*>(op) = o;
        }
    }
}

extern "C" void kernel_launch(void* const* d_in, const int* in_sizes, int n_in,
                              void* d_out, int out_size) {
    const float* x    = (const float*)d_in[0];   // (4,9,1024,1024)
    const float* rnd  = (const float*)d_in[1];   // (4,8,1024,1024)
    const float* drop = (const float*)d_in[2];   // (1024,1024)
    // d_in[3] = nn_kernel: fixed cross structure, baked into the kernel
    float* out = (float*)d_out;

    int grid = 4 * Hh;                           // one block per (batch, row) = 4096
    ising_step_kernel<<<grid, 256>>>(x, rnd, drop, out);
}

// round 7
// speedup vs baseline: 1.4641x; 1.0944x over previous
#include <cuda_runtime.h>

// Problem constants (fixed by the reference: B=4, C=8, H=W=1024, R=1 cross kernel, wrap pad)
constexpr int Hh = 1024;
constexpr int Ww = 1024;
constexpr int PLANE = Hh * Ww;          // 1,048,576
constexpr int W4 = Ww / 4;              // 256 float4 per row

// Accurate fp32 exp (Cody-Waite reduction + cephes degree-6 poly, ~1 ulp).
__device__ __forceinline__ float exp_acc(float x) {
    x = fminf(fmaxf(x, -87.3f), 88.0f);
    float n = rintf(x * 1.44269504088896341f);
    float r = fmaf(n, -0.693359375f, x);        // Cody-Waite hi
    r = fmaf(n, 2.12194440e-4f, r);             // Cody-Waite lo
    float rr = r * r;
    float y = 1.9875691500e-4f;
    y = fmaf(y, r, 1.3981999507e-3f);
    y = fmaf(y, r, 8.3334519073e-3f);
    y = fmaf(y, r, 4.1665795894e-2f);
    y = fmaf(y, r, 1.6666665459e-1f);
    y = fmaf(y, r, 5.0000001201e-1f);
    y = fmaf(y, rr, r);
    y = y + 1.0f;
    float sc = __int_as_float(((int)n + 127) << 23);
    return y * sc;
}

__device__ __forceinline__ float flip_one(float s, float J, float bf, float r, bool drop) {
    float de = 2.0f * s * J;
    bool flip;
    if (de <= 0.0f) {
        flip = drop;                            // p = 1, rand in [0,1) < 1 always
    } else {
        float p = exp_acc(-de * bf);
        flip = (r < p) && drop;
    }
    return flip ? -s : s;
}

__device__ __forceinline__ float4 ld_cs4(const float* p) {
    return __ldcs(reinterpret_cast<const float4*>(p));
}

// R2 structure + schedule, with one change: centers are stashed into a
// private smem slot in pass 1 and re-read from smem in pass 2 (instead of
// re-issuing 16 global loads). No barrier: each thread touches only its own
// smem slots. Cache policy identical to R2: centers default (fill L2 for the
// cross-row reuse), up/dn/rand .cs (streams).
__global__ __launch_bounds__(256, 6) void ising_step_kernel(
    const float* __restrict__ x,      // (4, 9, 1024, 1024): s = ch 0..7, b = ch 8
    const float* __restrict__ rnd,    // (4, 8, 1024, 1024)
    const float* __restrict__ drop,   // (1024, 1024)
    float* __restrict__ out)          // (4, 9, 1024, 1024)
{
    __shared__ float stash[8][Ww];    // 32 KB: [channel][tid*4 .. tid*4+3]

    int tid = blockIdx.x * blockDim.x + threadIdx.x;   // 0 .. 4*1024*256-1
    int w4 = tid & (W4 - 1);
    int h  = (tid >> 8) & (Hh - 1);
    int b  = tid >> 18;
    int w  = w4 * 4;
    int sw = threadIdx.x * 4;                           // this thread's smem column

    const float* xb = x + b * 9 * PLANE;
    int rowc = h * Ww;
    int rowu = ((h + Hh - 1) & (Hh - 1)) * Ww;   // wrap up
    int rowd = ((h + 1) & (Hh - 1)) * Ww;        // wrap down
    int wl = (w + Ww - 1) & (Ww - 1);            // wrap left of pixel 0
    int wr = (w + 4) & (Ww - 1);                 // wrap right of pixel 3

    // Pass 1: accumulate J; stash centers in private smem for pass 2.
    float4 J = make_float4(0.f, 0.f, 0.f, 0.f);
    #pragma unroll
    for (int c = 0; c < 8; c++) {
        const float* sp = xb + c * PLANE;
        float4 cc = *reinterpret_cast<const float4*>(sp + rowc + w);  // default: fills L2
        float4 up = ld_cs4(sp + rowu + w);       // streaming: L2 hit on center-filled line
        float4 dn = ld_cs4(sp + rowd + w);
        float lf = sp[rowc + wl];
        float rt = sp[rowc + wr];
        *reinterpret_cast<float4*>(&stash[c][sw]) = cc;
        J.x += (up.x + dn.x) + (lf   + cc.y);
        J.y += (up.y + dn.y) + (cc.x + cc.z);
        J.z += (up.z + dn.z) + (cc.y + cc.w);
        J.w += (up.w + dn.w) + (cc.z + rt);
    }

    // Field b and dropout mask for these 4 pixels
    float4 bf = *reinterpret_cast<const float4*>(xb + 8 * PLANE + rowc + w);
    float4 dv = *reinterpret_cast<const float4*>(drop + rowc + w);
    bool d0 = dv.x > 0.5f, d1 = dv.y > 0.5f, d2 = dv.z > 0.5f, d3 = dv.w > 0.5f;

    float* ob = out + b * 9 * PLANE;
    // Pass-through channel 8 (the field)
    *reinterpret_cast<float4*>(ob + 8 * PLANE + rowc + w) = bf;

    const float* rb = rnd + b * 8 * PLANE;
    #pragma unroll
    for (int c = 0; c < 8; c++) {
        float4 cc = *reinterpret_cast<const float4*>(&stash[c][sw]);  // own slot: no sync needed
        float4 rv = ld_cs4(rb + c * PLANE + rowc + w);                // read-once stream
        float4 o;
        o.x = flip_one(cc.x, J.x, bf.x, rv.x, d0);
        o.y = flip_one(cc.y, J.y, bf.y, rv.y, d1);
        o.z = flip_one(cc.z, J.z, bf.z, rv.z, d2);
        o.w = flip_one(cc.w, J.w, bf.w, rv.w, d3);
        *reinterpret_cast<float4*>(ob + c * PLANE + rowc + w) = o;
    }
}

extern "C" void kernel_launch(void* const* d_in, const int* in_sizes, int n_in,
                              void* d_out, int out_size) {
    const float* x    = (const float*)d_in[0];   // (4,9,1024,1024)
    const float* rnd  = (const float*)d_in[1];   // (4,8,1024,1024)
    const float* drop = (const float*)d_in[2];   // (1024,1024)
    // d_in[3] = nn_kernel: fixed cross structure, baked into the kernel
    float* out = (float*)d_out;

    int total_threads = 4 * Hh * W4;             // 1,048,576
    int block = 256;
    int grid = total_threads / block;            // 4096
    ising_step_kernel<<<grid, block>>>(x, rnd, drop, out);
}

// round 8
// speedup vs baseline: 1.9289x; 1.3175x over previous
#include <cuda_runtime.h>

// Problem constants (fixed by the reference: B=4, C=8, H=W=1024, R=1 cross kernel, wrap pad)
constexpr int Hh = 1024;
constexpr int Ww = 1024;
constexpr int PLANE = Hh * Ww;          // 1,048,576
constexpr int KR = 8;                   // rows per CTA strip
constexpr int STRIPS = Hh / KR;         // 128

// Accurate fp32 exp (Cody-Waite reduction + cephes degree-6 poly, ~1 ulp).
__device__ __forceinline__ float exp_acc(float x) {
    x = fminf(fmaxf(x, -87.3f), 88.0f);
    float n = rintf(x * 1.44269504088896341f);
    float r = fmaf(n, -0.693359375f, x);        // Cody-Waite hi
    r = fmaf(n, 2.12194440e-4f, r);             // Cody-Waite lo
    float rr = r * r;
    float y = 1.9875691500e-4f;
    y = fmaf(y, r, 1.3981999507e-3f);
    y = fmaf(y, r, 8.3334519073e-3f);
    y = fmaf(y, r, 4.1665795894e-2f);
    y = fmaf(y, r, 1.6666665459e-1f);
    y = fmaf(y, r, 5.0000001201e-1f);
    y = fmaf(y, rr, r);
    y = y + 1.0f;
    float sc = __int_as_float(((int)n + 127) << 23);
    return y * sc;
}

__device__ __forceinline__ float flip_one(float s, float J, float bf, float r, bool drop) {
    float de = 2.0f * s * J;
    bool flip;
    if (de <= 0.0f) {
        flip = drop;                            // p = 1, rand in [0,1) < 1 always
    } else {
        float p = exp_acc(-de * bf);
        flip = (r < p) && drop;
    }
    return flip ? -s : s;
}

__device__ __forceinline__ float4 ld4(const float* p) {
    return *reinterpret_cast<const float4*>(p);
}
__device__ __forceinline__ float4 ld_cs4(const float* p) {
    return __ldcs(reinterpret_cast<const float4*>(p));
}

// Key identity: the conv kernel is the same cross for all channels with ONE
// output channel, so J(h,w) = S(h-1,w)+S(h+1,w)+S(h,w-1)+S(h,w+1) where
// S = sum_c s_c. One CTA = one (batch, 8-row strip); 256 threads cover a full
// 1024-px row and walk down, keeping a rolling 3-row S buffer in smem (12 KB).
// Each s element is loaded from DRAM ~1.25x total (vs 3x touches in R2),
// eliminating all per-channel neighbor loads.
__global__ __launch_bounds__(256, 4) void ising_step_kernel(
    const float* __restrict__ x,      // (4, 9, 1024, 1024): s = ch 0..7, b = ch 8
    const float* __restrict__ rnd,    // (4, 8, 1024, 1024)
    const float* __restrict__ drop,   // (1024, 1024)
    float* __restrict__ out)          // (4, 9, 1024, 1024)
{
    __shared__ float S[3][Ww];        // rolling channel-sum rows: logical row (h0-1+j) in slot j%3

    int b     = blockIdx.x >> 7;                 // 4 batches
    int strip = blockIdx.x & (STRIPS - 1);
    int h0    = strip * KR;
    int w     = threadIdx.x * 4;
    int wl    = (w + Ww - 1) & (Ww - 1);         // left-of-pixel-0 (row wrap, in-block)
    int wr    = (w + 4) & (Ww - 1);              // right-of-pixel-3

    const float* xb = x + b * 9 * PLANE;
    const float* rb = rnd + b * 8 * PLANE;
    float* ob = out + b * 9 * PLANE;

    // Prologue: S(h0-1) -> slot 0, S(h0) -> slot 1.
    #pragma unroll
    for (int j = 0; j < 2; j++) {
        int h = (h0 + Hh - 1 + j) & (Hh - 1);
        const float* sp = xb + h * Ww + w;
        float4 cv[8];
        #pragma unroll
        for (int c = 0; c < 8; c++) cv[c] = ld4(sp + c * PLANE);
        float4 s4 = make_float4(0.f, 0.f, 0.f, 0.f);
        #pragma unroll
        for (int c = 0; c < 8; c++) {
            s4.x += cv[c].x; s4.y += cv[c].y; s4.z += cv[c].z; s4.w += cv[c].w;
        }
        *reinterpret_cast<float4*>(&S[j][w]) = s4;
    }

    #pragma unroll 1
    for (int i = 0; i < KR; i++) {
        int hc = h0 + i;                          // output row (never wraps: h0+i <= 1023)
        int hn = (hc + 1) & (Hh - 1);             // next row for S (wraps at strip end)

        // Phase 1: load next row's 8 channels (independent DRAM misses), sum to S.
        const float* spn = xb + hn * Ww + w;
        float4 cv[8];
        #pragma unroll
        for (int c = 0; c < 8; c++) cv[c] = ld4(spn + c * PLANE);
        float4 s4 = make_float4(0.f, 0.f, 0.f, 0.f);
        #pragma unroll
        for (int c = 0; c < 8; c++) {
            s4.x += cv[c].x; s4.y += cv[c].y; s4.z += cv[c].z; s4.w += cv[c].w;
        }
        __syncthreads();                          // prior iteration's readers of this slot are done
        *reinterpret_cast<float4*>(&S[(i + 2) % 3][w]) = s4;
        __syncthreads();                          // S(hn) visible to all

        // Phase 2: J for row hc from the 3 S rows in smem.
        const float* Su = S[i % 3];               // S(hc-1)
        const float* Sc = S[(i + 1) % 3];         // S(hc)
        const float* Sd = S[(i + 2) % 3];         // S(hc+1)
        float4 su = *reinterpret_cast<const float4*>(&Su[w]);
        float4 sc = *reinterpret_cast<const float4*>(&Sc[w]);
        float4 sd = *reinterpret_cast<const float4*>(&Sd[w]);
        float lf = Sc[wl], rt = Sc[wr];
        float4 J;
        J.x = (su.x + sd.x) + (lf   + sc.y);
        J.y = (su.y + sd.y) + (sc.x + sc.z);
        J.z = (su.z + sd.z) + (sc.y + sc.w);
        J.w = (su.w + sd.w) + (sc.z + rt);

        // Phase 3: flips for row hc.
        int rowc = hc * Ww + w;
        float4 bf = ld4(xb + 8 * PLANE + rowc);
        float4 dv = ld4(drop + rowc);
        bool d0 = dv.x > 0.5f, d1 = dv.y > 0.5f, d2 = dv.z > 0.5f, d3 = dv.w > 0.5f;
        *reinterpret_cast<float4*>(ob + 8 * PLANE + rowc) = bf;   // pass-through field

        #pragma unroll
        for (int c = 0; c < 8; c++) {
            float4 cc = ld4(xb + c * PLANE + rowc);   // loaded last iteration -> L1/L2 hit
            float4 rv = ld_cs4(rb + c * PLANE + rowc);// read-once stream
            float4 o;
            o.x = flip_one(cc.x, J.x, bf.x, rv.x, d0);
            o.y = flip_one(cc.y, J.y, bf.y, rv.y, d1);
            o.z = flip_one(cc.z, J.z, bf.z, rv.z, d2);
            o.w = flip_one(cc.w, J.w, bf.w, rv.w, d3);
            *reinterpret_cast<float4*>(ob + c * PLANE + rowc) = o;
        }
    }
}

extern "C" void kernel_launch(void* const* d_in, const int* in_sizes, int n_in,
                              void* d_out, int out_size) {
    const float* x    = (const float*)d_in[0];   // (4,9,1024,1024)
    const float* rnd  = (const float*)d_in[1];   // (4,8,1024,1024)
    const float* drop = (const float*)d_in[2];   // (1024,1024)
    // d_in[3] = nn_kernel: fixed cross structure, baked into the kernel
    float* out = (float*)d_out;

    int grid = 4 * STRIPS;                       // 512 CTAs, single wave at occ>=4
    ising_step_kernel<<<grid, 256>>>(x, rnd, drop, out);
}